// round 13
// baseline (speedup 1.0000x reference)
#include <cuda_runtime.h>

#define BB 2
#define KK 4
#define DD 128
#define HH 128
#define WW 128
#define NN (DD*HH*WW)          // 2097152
#define TY 8
#define TZ 16
#define NBLK ((DD/TZ)*(HH/TY)*BB)   // 8*16*2 = 256 blocks
#define REG_WT 0.0008

// ---------------- global scratch (no allocs allowed) ----------------
__device__ double   g_part[NBLK][10];  // per-block partials: B[4],C[4],A,J2
__device__ unsigned g_ticket;          // zero-init at load; last block resets to 0

__device__ __forceinline__ float warp_red(float v) {
    #pragma unroll
    for (int o = 16; o > 0; o >>= 1) v += __shfl_down_sync(0xffffffffu, v, o);
    return v;
}

// Single fused kernel: R7 pass2 body (static smem, LDG img) + moment reductions.
// block = (32, 8): warp w owns y-row y0+w (full x = 32 lanes x float4).
__global__ __launch_bounds__(256, 2) void rfcm_kernel(const float* __restrict__ yp,
                                                      const float* __restrict__ img,
                                                      float* __restrict__ out) {
    const int lane = threadIdx.x;          // 0..31 -> x quad [4*lane, 4*lane+3]
    const int w    = threadIdx.y;          // 0..7 warp id == y row in tile
    const int zc = blockIdx.x;             // 0..7
    const int yt = blockIdx.y;             // 0..15
    const int b  = blockIdx.z;             // 0..1
    const int y0 = yt * TY;
    const int z0 = zc * TZ;
    const int bid = zc + (DD/TZ)*yt + (DD/TZ)*(HH/TY)*b;

    __shared__ float4 raw[2][KK][TY+2][32];   // RAW p values (squared on read)
    __shared__ float  red[10][8];
    __shared__ double fin[18];
    __shared__ unsigned s_last;

    const float* __restrict__ imb = img + (size_t)b * NN;

    // issue cp.async loads for plane pz into raw[pz&1] (40 rows over 8 warps)
    auto issue_plane = [&](int pz) {
        const int buf = pz & 1;
        const bool zok = (pz >= 0) && (pz < DD);
        #pragma unroll
        for (int i = 0; i < 5; i++) {
            int r  = w + 8*i;              // 0..39
            int c  = r / 10;
            int yy = r - 10*c;
            int gyy = y0 + yy - 1;
            bool ok = zok && (gyy >= 0) && (gyy < HH);
            const float* src = yp + ((size_t)(b*KK + c))*NN
                                  + (size_t)(ok ? pz : 0)*(HH*WW)
                                  + (size_t)(ok ? gyy : 0)*WW + 4*lane;
            unsigned dst = (unsigned)__cvta_generic_to_shared(&raw[buf][c][yy][lane]);
            int sz = ok ? 16 : 0;          // src-size 0 -> zero-fill
            asm volatile("cp.async.cg.shared.global [%0], [%1], 16, %2;\n"
                         :: "r"(dst), "l"(src), "r"(sz));
        }
        asm volatile("cp.async.commit_group;\n");
    };

    // z-ring registers (per channel, float4 lanes):
    // sA = s_{pz-1}, sB = s_{pz-2}+s_{pz-1}, mP = center mem of plane pz-1
    float4 sA[KK], sB[KK], mP[KK];
    #pragma unroll
    for (int c = 0; c < KK; c++) {
        sA[c] = make_float4(0,0,0,0);
        sB[c] = make_float4(0,0,0,0);
        mP[c] = make_float4(0,0,0,0);
    }
    float Atot = 0.f, aJ2 = 0.f;       // sum mem_tot*img^2 ; J2 partial
    float Bcc[KK] = {0,0,0,0};         // sum mem*img  (per channel)
    float Ccc[KK] = {0,0,0,0};         // sum mem      (per channel)

    issue_plane(z0 - 1);

    for (int pz = z0 - 1; pz <= z0 + TZ; ++pz) {
        const int buf = pz & 1;

        asm volatile("cp.async.wait_group 0;\n" ::: "memory");  // plane pz resident
        __syncthreads();
        if (pz < z0 + TZ) issue_plane(pz + 1);  // next plane flies during compute

        const bool emit = (pz > z0);
        float4 iv = make_float4(0,0,0,0);
        if (emit) {
            iv = *(const float4*)(imb + (size_t)(pz-1)*(HH*WW) + (size_t)(y0+w)*WW + 4*lane);
        }
        float4 Ms = make_float4(0,0,0,0), Tnb = make_float4(0,0,0,0);
        float4 dmn = make_float4(0,0,0,0);

        #pragma unroll
        for (int c = 0; c < KK; c++) {
            // vertical 3-tap from smem (square on read: mem = p^2)
            float4 r0 = raw[buf][c][w  ][lane];
            float4 r1 = raw[buf][c][w+1][lane];
            float4 r2 = raw[buf][c][w+2][lane];
            r0.x *= r0.x; r0.y *= r0.y; r0.z *= r0.z; r0.w *= r0.w;
            r1.x *= r1.x; r1.y *= r1.y; r1.z *= r1.z; r1.w *= r1.w;
            r2.x *= r2.x; r2.y *= r2.y; r2.z *= r2.z; r2.w *= r2.w;
            float4 ry;
            ry.x = r0.x + r1.x + r2.x;
            ry.y = r0.y + r1.y + r2.y;
            ry.z = r0.z + r1.z + r2.z;
            ry.w = r0.w + r1.w + r2.w;
            // horizontal 3-tap via shuffles (warp spans full x-row)
            float lf = __shfl_up_sync  (0xffffffffu, ry.w, 1);
            float rt = __shfl_down_sync(0xffffffffu, ry.x, 1);
            lf = (lane == 0)  ? 0.f : lf;
            rt = (lane == 31) ? 0.f : rt;
            float4 s;                       // 2D 3x3 sum at plane pz
            s.x = lf   + ry.x + ry.y;
            s.y = ry.x + ry.y + ry.z;
            s.z = ry.y + ry.z + ry.w;
            s.w = ry.z + ry.w + rt;

            if (emit) {
                float4 m = mP[c];           // mem at plane pz-1 center
                float4 box, nb;
                box.x = sB[c].x + s.x;  box.y = sB[c].y + s.y;
                box.z = sB[c].z + s.z;  box.w = sB[c].w + s.w;
                nb.x = box.x - m.x; nb.y = box.y - m.y;
                nb.z = box.z - m.z; nb.w = box.w - m.w;
                Ms.x += m.x; Ms.y += m.y; Ms.z += m.z; Ms.w += m.w;
                Tnb.x += nb.x; Tnb.y += nb.y; Tnb.z += nb.z; Tnb.w += nb.w;
                dmn.x += m.x*nb.x; dmn.y += m.y*nb.y;
                dmn.z += m.z*nb.z; dmn.w += m.w*nb.w;
                Ccc[c] += (m.x + m.y) + (m.z + m.w);
                Bcc[c] += m.x*iv.x + m.y*iv.y + m.z*iv.z + m.w*iv.w;
            }
            // ring update
            sB[c].x = sA[c].x + s.x; sB[c].y = sA[c].y + s.y;
            sB[c].z = sA[c].z + s.z; sB[c].w = sA[c].w + s.w;
            sA[c] = s;
            mP[c] = r1;
        }
        if (emit) {
            // sum_ch mem*img^2 = Ms . iv^2  (total membership trick)
            Atot += Ms.x*iv.x*iv.x + Ms.y*iv.y*iv.y + Ms.z*iv.z*iv.z + Ms.w*iv.w*iv.w;
            aJ2  += (Tnb.x*Ms.x - dmn.x) + (Tnb.y*Ms.y - dmn.y)
                  + (Tnb.z*Ms.z - dmn.z) + (Tnb.w*Ms.w - dmn.w);
        }
    }

    // ---- block reduce 10 scalars -> g_part[bid] ----
    float vals[10];
    #pragma unroll
    for (int c = 0; c < KK; c++) { vals[c] = Bcc[c]; vals[4+c] = Ccc[c]; }
    vals[8] = Atot; vals[9] = aJ2;
    #pragma unroll
    for (int j = 0; j < 10; j++) {
        float v = warp_red(vals[j]);
        if (lane == 0) red[j][w] = v;
    }
    __syncthreads();
    if (w == 0) {
        #pragma unroll
        for (int j = 0; j < 10; j++) {
            float v = (lane < 8) ? red[j][lane] : 0.f;
            v = warp_red(v);
            if (lane == 0) g_part[bid][j] = (double)v;
        }
    }
    __threadfence();
    __syncthreads();
    const int tid = w*32 + lane;
    if (tid == 0) s_last = (atomicAdd(&g_ticket, 1u) == NBLK - 1) ? 1u : 0u;
    __syncthreads();

    if (s_last) {
        __threadfence();            // acquire: other blocks' g_part now visible
        if (tid < 18) fin[tid] = 0.0;   // fin: B[8], C[8], A, J2
        __syncthreads();
        if (tid < NBLK) {           // 256 threads, one per block's partials
            int bb = tid >> 7;      // batch of that block
            #pragma unroll
            for (int c = 0; c < KK; c++) {
                atomicAdd(&fin[bb*KK + c],     g_part[tid][c]);      // B
                atomicAdd(&fin[8 + bb*KK + c], g_part[tid][4 + c]);  // C
            }
            atomicAdd(&fin[16], g_part[tid][8]);                     // A
            atomicAdd(&fin[17], g_part[tid][9]);                     // J2
        }
        __syncthreads();
        if (tid == 0) {
            double J1 = fin[16];
            #pragma unroll
            for (int ch = 0; ch < BB*KK; ch++)
                J1 -= fin[ch]*fin[ch] / fin[8+ch];
            double denom = (double)BB * (double)NN;
            out[0] = (float)((J1 + REG_WT * fin[17]) / denom);
            g_ticket = 0u;          // self-reset for next launch
        }
    }
}

extern "C" void kernel_launch(void* const* d_in, const int* in_sizes, int n_in,
                              void* d_out, int out_size) {
    const float* yp  = (const float*)d_in[0];   // y_pred [2,4,128,128,128]
    const float* img = (const float*)d_in[1];   // image  [2,1,128,128,128]
    (void)in_sizes; (void)n_in; (void)out_size;

    rfcm_kernel<<<dim3(DD/TZ, HH/TY, BB), dim3(32, TY)>>>(yp, img, (float*)d_out);
}

// round 15
// speedup vs baseline: 1.6015x; 1.6015x over previous
#include <cuda_runtime.h>

#define BB 2
#define KK 4
#define DD 128
#define HH 128
#define WW 128
#define NN (DD*HH*WW)          // 2097152
#define TY 8
#define TZ 16
#define NBX 64                 // pass1 x-blocks
#define NBLK2 ((DD/TZ)*(HH/TY)*BB)   // 8*16*2 = 256 pass2 blocks
#define REG_WT 0.0008

// ---------------- global scratch (no allocs allowed) ----------------
__device__ float    g_pA[BB*KK][NBX];  // per-block sum(mem*img^2)
__device__ float    g_pB[BB*KK][NBX];  // per-block sum(mem*img)
__device__ float    g_pC[BB*KK][NBX];  // per-block sum(mem)
__device__ double   g_J2;
__device__ unsigned g_ticket;

__device__ __forceinline__ float warp_red(float v) {
    #pragma unroll
    for (int o = 16; o > 0; o >>= 1) v += __shfl_down_sync(0xffffffffu, v, o);
    return v;
}

// ---------------- pass 1: per-(b,k) J1 moments A,B,C (atomic-free) ----------
__global__ __launch_bounds__(256) void pass1_kernel(const float* __restrict__ yp,
                                                    const float* __restrict__ img) {
    const int ch = blockIdx.y;             // 0..7 = b*4+k
    const int b  = ch >> 2;
    const float4* __restrict__ p  = (const float4*)(yp  + (size_t)ch * NN);
    const float4* __restrict__ im = (const float4*)(img + (size_t)b  * NN);

    float sa = 0.f, sb = 0.f, sc = 0.f;
    const int stride = gridDim.x * blockDim.x;
    for (int i = blockIdx.x * blockDim.x + threadIdx.x; i < NN/4; i += stride) {
        float4 pv = p[i];
        float4 iv = im[i];
        float m0 = pv.x*pv.x, m1 = pv.y*pv.y, m2 = pv.z*pv.z, m3 = pv.w*pv.w;
        sc += (m0 + m1) + (m2 + m3);
        float b0 = m0*iv.x, b1 = m1*iv.y, b2 = m2*iv.z, b3 = m3*iv.w;
        sb += (b0 + b1) + (b2 + b3);
        sa += b0*iv.x + b1*iv.y + b2*iv.z + b3*iv.w;
    }

    __shared__ float r1[8], r2[8], r3[8];
    sa = warp_red(sa); sb = warp_red(sb); sc = warp_red(sc);
    int lane = threadIdx.x & 31, w = threadIdx.x >> 5;
    if (lane == 0) { r1[w] = sa; r2[w] = sb; r3[w] = sc; }
    __syncthreads();
    if (w == 0) {
        float a = (lane < 8) ? r1[lane] : 0.f;
        float c = (lane < 8) ? r2[lane] : 0.f;
        float d = (lane < 8) ? r3[lane] : 0.f;
        a = warp_red(a); c = warp_red(c); d = warp_red(d);
        if (lane == 0) {
            g_pA[ch][blockIdx.x] = a;
            g_pB[ch][blockIdx.x] = c;
            g_pC[ch][blockIdx.x] = d;
        }
    }
    if (blockIdx.x == 0 && blockIdx.y == 0 && threadIdx.x == 0) {
        g_J2 = 0.0; g_ticket = 0u;
    }
}

// ---------------- pass 2: J2-only sliding-window stencil + final combine ----
// block = (32, 8): warp w owns y-row y0+w (full x = 32 lanes x float4).
// Center-plane mem re-read from the other smem buffer (no mP register ring).
__global__ __launch_bounds__(256, 3) void pass2_kernel(const float* __restrict__ yp,
                                                       float* __restrict__ out) {
    const int lane = threadIdx.x;          // 0..31 -> x quad [4*lane, 4*lane+3]
    const int w    = threadIdx.y;          // 0..7 warp id == y row in tile
    const int zc = blockIdx.x;             // 0..7
    const int yt = blockIdx.y;             // 0..15
    const int b  = blockIdx.z;             // 0..1
    const int y0 = yt * TY;
    const int z0 = zc * TZ;

    __shared__ float4 raw[2][KK][TY+2][32];   // RAW p values (squared on read)
    __shared__ float  s1[8];
    __shared__ double jsh[KK*BB >= 8 ? 9 : 9];  // 8 per-ch J1 terms + spare
    __shared__ unsigned s_last;

    // issue cp.async loads for plane pz into raw[pz&1] (40 rows over 8 warps)
    auto issue_plane = [&](int pz) {
        const int buf = pz & 1;
        const bool zok = (pz >= 0) && (pz < DD);
        #pragma unroll
        for (int i = 0; i < 5; i++) {
            int r  = w + 8*i;              // 0..39
            int c  = r / 10;
            int yy = r - 10*c;
            int gyy = y0 + yy - 1;
            bool ok = zok && (gyy >= 0) && (gyy < HH);
            const float* src = yp + ((size_t)(b*KK + c))*NN
                                  + (size_t)(ok ? pz : 0)*(HH*WW)
                                  + (size_t)(ok ? gyy : 0)*WW + 4*lane;
            unsigned dst = (unsigned)__cvta_generic_to_shared(&raw[buf][c][yy][lane]);
            int sz = ok ? 16 : 0;          // src-size 0 -> zero-fill
            asm volatile("cp.async.cg.shared.global [%0], [%1], 16, %2;\n"
                         :: "r"(dst), "l"(src), "r"(sz));
        }
        asm volatile("cp.async.commit_group;\n");
    };

    // z-ring registers: sA = s_{pz-1}, sB = s_{pz-2}+s_{pz-1}
    float4 sA[KK], sB[KK];
    #pragma unroll
    for (int c = 0; c < KK; c++) {
        sA[c] = make_float4(0,0,0,0);
        sB[c] = make_float4(0,0,0,0);
    }
    float aJ2 = 0.f;

    issue_plane(z0 - 1);

    for (int pz = z0 - 1; pz <= z0 + TZ; ++pz) {
        const int buf = pz & 1;

        asm volatile("cp.async.wait_group 0;\n" ::: "memory");  // plane pz resident
        __syncthreads();

        const bool emit = (pz > z0);
        // center mem of plane pz-1 from the OTHER buffer (still intact)
        float4 mloc[KK];
        if (emit) {
            #pragma unroll
            for (int c = 0; c < KK; c++) {
                float4 m = raw[buf^1][c][w+1][lane];
                m.x *= m.x; m.y *= m.y; m.z *= m.z; m.w *= m.w;
                mloc[c] = m;
            }
        }
        __syncthreads();                    // all prev-buffer reads done
        if (pz < z0 + TZ) issue_plane(pz + 1);  // overwrites buf^1 during compute

        float4 Ms = make_float4(0,0,0,0), Tnb = make_float4(0,0,0,0);
        float4 dmn = make_float4(0,0,0,0);

        #pragma unroll
        for (int c = 0; c < KK; c++) {
            // vertical 3-tap from smem (square on read: mem = p^2)
            float4 r0 = raw[buf][c][w  ][lane];
            float4 r1 = raw[buf][c][w+1][lane];
            float4 r2 = raw[buf][c][w+2][lane];
            r0.x *= r0.x; r0.y *= r0.y; r0.z *= r0.z; r0.w *= r0.w;
            r1.x *= r1.x; r1.y *= r1.y; r1.z *= r1.z; r1.w *= r1.w;
            r2.x *= r2.x; r2.y *= r2.y; r2.z *= r2.z; r2.w *= r2.w;
            float4 ry;
            ry.x = r0.x + r1.x + r2.x;
            ry.y = r0.y + r1.y + r2.y;
            ry.z = r0.z + r1.z + r2.z;
            ry.w = r0.w + r1.w + r2.w;
            // horizontal 3-tap via shuffles (warp spans full x-row)
            float lf = __shfl_up_sync  (0xffffffffu, ry.w, 1);
            float rt = __shfl_down_sync(0xffffffffu, ry.x, 1);
            lf = (lane == 0)  ? 0.f : lf;
            rt = (lane == 31) ? 0.f : rt;
            float4 s;                       // 2D 3x3 sum at plane pz
            s.x = lf   + ry.x + ry.y;
            s.y = ry.x + ry.y + ry.z;
            s.z = ry.y + ry.z + ry.w;
            s.w = ry.z + ry.w + rt;

            if (emit) {
                float4 m = mloc[c];
                float4 box, nb;
                box.x = sB[c].x + s.x;  box.y = sB[c].y + s.y;
                box.z = sB[c].z + s.z;  box.w = sB[c].w + s.w;
                nb.x = box.x - m.x; nb.y = box.y - m.y;
                nb.z = box.z - m.z; nb.w = box.w - m.w;
                Ms.x += m.x; Ms.y += m.y; Ms.z += m.z; Ms.w += m.w;
                Tnb.x += nb.x; Tnb.y += nb.y; Tnb.z += nb.z; Tnb.w += nb.w;
                dmn.x += m.x*nb.x; dmn.y += m.y*nb.y;
                dmn.z += m.z*nb.z; dmn.w += m.w*nb.w;
            }
            // ring update
            sB[c].x = sA[c].x + s.x; sB[c].y = sA[c].y + s.y;
            sB[c].z = sA[c].z + s.z; sB[c].w = sA[c].w + s.w;
            sA[c] = s;
        }
        if (emit) {
            aJ2 += (Tnb.x*Ms.x - dmn.x) + (Tnb.y*Ms.y - dmn.y)
                 + (Tnb.z*Ms.z - dmn.z) + (Tnb.w*Ms.w - dmn.w);
        }
    }

    // ---- block reduce J2 -> one double atomic per block ----
    aJ2 = warp_red(aJ2);
    if (lane == 0) s1[w] = aJ2;
    __syncthreads();
    const int tid = w*32 + lane;
    if (w == 0) {
        float v = (lane < 8) ? s1[lane] : 0.f;
        v = warp_red(v);
        if (lane == 0) {
            atomicAdd(&g_J2, (double)v);
            __threadfence();
            s_last = (atomicAdd(&g_ticket, 1u) == NBLK2 - 1) ? 1u : 0u;
        }
    }
    __syncthreads();

    if (s_last) {
        __threadfence();            // acquire: all g_J2 adds visible
        // warp w = channel w (8 channels): reduce pass1 partials
        if (w < BB*KK) {
            float A = g_pA[w][lane] + g_pA[w][lane+32];
            float B = g_pB[w][lane] + g_pB[w][lane+32];
            float C = g_pC[w][lane] + g_pC[w][lane+32];
            A = warp_red(A); B = warp_red(B); C = warp_red(C);
            if (lane == 0) jsh[w] = (double)A - (double)B*(double)B/(double)C;
        }
        __syncthreads();
        if (tid == 0) {
            double J1 = 0.0;
            #pragma unroll
            for (int ch = 0; ch < BB*KK; ch++) J1 += jsh[ch];
            double J2 = atomicAdd(&g_J2, 0.0);
            double denom = (double)BB * (double)NN;
            out[0] = (float)((J1 + REG_WT * J2) / denom);
        }
    }
}

extern "C" void kernel_launch(void* const* d_in, const int* in_sizes, int n_in,
                              void* d_out, int out_size) {
    const float* yp  = (const float*)d_in[0];   // y_pred [2,4,128,128,128]
    const float* img = (const float*)d_in[1];   // image  [2,1,128,128,128]
    (void)in_sizes; (void)n_in; (void)out_size;

    pass1_kernel<<<dim3(NBX, BB*KK), 256>>>(yp, img);
    pass2_kernel<<<dim3(DD/TZ, HH/TY, BB), dim3(32, TY)>>>(yp, (float*)d_out);
}

// round 16
// speedup vs baseline: 1.7132x; 1.0697x over previous
#include <cuda_runtime.h>

#define BB 2
#define KK 4
#define DD 128
#define HH 128
#define WW 128
#define NN (DD*HH*WW)          // 2097152
#define TY 8
#define TZ 16
#define NBX 16                 // pass1 x-blocks per channel
#define NP1 (BB*KK*NBX)        // 128 pass1-role blocks
#define NBLK2 ((DD/TZ)*(HH/TY)*BB)   // 256 pass2-role blocks
#define NTOT (NBLK2 + NP1)     // 384 total blocks
#define REG_WT 0.0008

// ---------------- global scratch (no allocs allowed) ----------------
__device__ float    g_pA[BB*KK][NBX];  // per-block sum(mem*img^2)
__device__ float    g_pB[BB*KK][NBX];  // per-block sum(mem*img)
__device__ float    g_pC[BB*KK][NBX];  // per-block sum(mem)
__device__ double   g_J2;              // zero at load; last block resets
__device__ unsigned g_ticket;          // zero at load; last block resets

__device__ __forceinline__ float warp_red(float v) {
    #pragma unroll
    for (int o = 16; o > 0; o >>= 1) v += __shfl_down_sync(0xffffffffu, v, o);
    return v;
}

// One launch, block-role split:
//   blocks [0, NBLK2)      : J2 stencil (proven R15 pass2 body, untouched)
//   blocks [NBLK2, NTOT)   : J1 moments A,B,C per (b,k) channel
// Last finisher (ticket) combines everything and writes out.
__global__ __launch_bounds__(256, 3) void rfcm_kernel(const float* __restrict__ yp,
                                                      const float* __restrict__ img,
                                                      float* __restrict__ out) {
    const int lane = threadIdx.x;          // 0..31
    const int w    = threadIdx.y;          // 0..7
    const int tid  = w*32 + lane;
    const int bx   = blockIdx.x;

    __shared__ float4 raw[2][KK][TY+2][32];   // RAW p values (squared on read)
    __shared__ float  s1[8], s2[8], s3[8];
    __shared__ double jsh[BB*KK];
    __shared__ unsigned s_last;

    if (bx >= NBLK2) {
        // ================= pass1 role: J1 moments =================
        const int p1 = bx - NBLK2;
        const int ch = p1 >> 4;            // 0..7 = b*4+k
        const int xb = p1 & (NBX-1);       // 0..15
        const int b  = ch >> 2;
        const float4* __restrict__ p  = (const float4*)(yp  + (size_t)ch * NN);
        const float4* __restrict__ im = (const float4*)(img + (size_t)b  * NN);

        float sa = 0.f, sb = 0.f, sc = 0.f;
        for (int i = xb*256 + tid; i < NN/4; i += NBX*256) {
            float4 pv = p[i];
            float4 iv = im[i];
            float m0 = pv.x*pv.x, m1 = pv.y*pv.y, m2 = pv.z*pv.z, m3 = pv.w*pv.w;
            sc += (m0 + m1) + (m2 + m3);
            float b0 = m0*iv.x, b1 = m1*iv.y, b2 = m2*iv.z, b3 = m3*iv.w;
            sb += (b0 + b1) + (b2 + b3);
            sa += b0*iv.x + b1*iv.y + b2*iv.z + b3*iv.w;
        }
        sa = warp_red(sa); sb = warp_red(sb); sc = warp_red(sc);
        if (lane == 0) { s1[w] = sa; s2[w] = sb; s3[w] = sc; }
        __syncthreads();
        if (w == 0) {
            float a = (lane < 8) ? s1[lane] : 0.f;
            float c = (lane < 8) ? s2[lane] : 0.f;
            float d = (lane < 8) ? s3[lane] : 0.f;
            a = warp_red(a); c = warp_red(c); d = warp_red(d);
            if (lane == 0) {
                g_pA[ch][xb] = a;
                g_pB[ch][xb] = c;
                g_pC[ch][xb] = d;
            }
        }
    } else {
        // ================= pass2 role: J2 stencil =================
        const int zc = bx & 7;             // 0..7
        const int yt = (bx >> 3) & 15;     // 0..15
        const int b  = bx >> 7;            // 0..1
        const int y0 = yt * TY;
        const int z0 = zc * TZ;

        auto issue_plane = [&](int pz) {
            const int buf = pz & 1;
            const bool zok = (pz >= 0) && (pz < DD);
            #pragma unroll
            for (int i = 0; i < 5; i++) {
                int r  = w + 8*i;              // 0..39
                int c  = r / 10;
                int yy = r - 10*c;
                int gyy = y0 + yy - 1;
                bool ok = zok && (gyy >= 0) && (gyy < HH);
                const float* src = yp + ((size_t)(b*KK + c))*NN
                                      + (size_t)(ok ? pz : 0)*(HH*WW)
                                      + (size_t)(ok ? gyy : 0)*WW + 4*lane;
                unsigned dst = (unsigned)__cvta_generic_to_shared(&raw[buf][c][yy][lane]);
                int sz = ok ? 16 : 0;          // src-size 0 -> zero-fill
                asm volatile("cp.async.cg.shared.global [%0], [%1], 16, %2;\n"
                             :: "r"(dst), "l"(src), "r"(sz));
            }
            asm volatile("cp.async.commit_group;\n");
        };

        float4 sA[KK], sB[KK];
        #pragma unroll
        for (int c = 0; c < KK; c++) {
            sA[c] = make_float4(0,0,0,0);
            sB[c] = make_float4(0,0,0,0);
        }
        float aJ2 = 0.f;

        issue_plane(z0 - 1);

        for (int pz = z0 - 1; pz <= z0 + TZ; ++pz) {
            const int buf = pz & 1;

            asm volatile("cp.async.wait_group 0;\n" ::: "memory");
            __syncthreads();

            const bool emit = (pz > z0);
            float4 mloc[KK];
            if (emit) {
                #pragma unroll
                for (int c = 0; c < KK; c++) {
                    float4 m = raw[buf^1][c][w+1][lane];
                    m.x *= m.x; m.y *= m.y; m.z *= m.z; m.w *= m.w;
                    mloc[c] = m;
                }
            }
            __syncthreads();                    // prev-buffer reads done
            if (pz < z0 + TZ) issue_plane(pz + 1);

            float4 Ms = make_float4(0,0,0,0), Tnb = make_float4(0,0,0,0);
            float4 dmn = make_float4(0,0,0,0);

            #pragma unroll
            for (int c = 0; c < KK; c++) {
                float4 r0 = raw[buf][c][w  ][lane];
                float4 r1 = raw[buf][c][w+1][lane];
                float4 r2 = raw[buf][c][w+2][lane];
                r0.x *= r0.x; r0.y *= r0.y; r0.z *= r0.z; r0.w *= r0.w;
                r1.x *= r1.x; r1.y *= r1.y; r1.z *= r1.z; r1.w *= r1.w;
                r2.x *= r2.x; r2.y *= r2.y; r2.z *= r2.z; r2.w *= r2.w;
                float4 ry;
                ry.x = r0.x + r1.x + r2.x;
                ry.y = r0.y + r1.y + r2.y;
                ry.z = r0.z + r1.z + r2.z;
                ry.w = r0.w + r1.w + r2.w;
                float lf = __shfl_up_sync  (0xffffffffu, ry.w, 1);
                float rt = __shfl_down_sync(0xffffffffu, ry.x, 1);
                lf = (lane == 0)  ? 0.f : lf;
                rt = (lane == 31) ? 0.f : rt;
                float4 s;                       // 2D 3x3 sum at plane pz
                s.x = lf   + ry.x + ry.y;
                s.y = ry.x + ry.y + ry.z;
                s.z = ry.y + ry.z + ry.w;
                s.w = ry.z + ry.w + rt;

                if (emit) {
                    float4 m = mloc[c];
                    float4 box, nb;
                    box.x = sB[c].x + s.x;  box.y = sB[c].y + s.y;
                    box.z = sB[c].z + s.z;  box.w = sB[c].w + s.w;
                    nb.x = box.x - m.x; nb.y = box.y - m.y;
                    nb.z = box.z - m.z; nb.w = box.w - m.w;
                    Ms.x += m.x; Ms.y += m.y; Ms.z += m.z; Ms.w += m.w;
                    Tnb.x += nb.x; Tnb.y += nb.y; Tnb.z += nb.z; Tnb.w += nb.w;
                    dmn.x += m.x*nb.x; dmn.y += m.y*nb.y;
                    dmn.z += m.z*nb.z; dmn.w += m.w*nb.w;
                }
                sB[c].x = sA[c].x + s.x; sB[c].y = sA[c].y + s.y;
                sB[c].z = sA[c].z + s.z; sB[c].w = sA[c].w + s.w;
                sA[c] = s;
            }
            if (emit) {
                aJ2 += (Tnb.x*Ms.x - dmn.x) + (Tnb.y*Ms.y - dmn.y)
                     + (Tnb.z*Ms.z - dmn.z) + (Tnb.w*Ms.w - dmn.w);
            }
        }

        aJ2 = warp_red(aJ2);
        if (lane == 0) s1[w] = aJ2;
        __syncthreads();
        if (w == 0) {
            float v = (lane < 8) ? s1[lane] : 0.f;
            v = warp_red(v);
            if (lane == 0) atomicAdd(&g_J2, (double)v);
        }
    }

    // ================= common tail: ticket + last-block combine =================
    __threadfence();
    __syncthreads();
    if (tid == 0) s_last = (atomicAdd(&g_ticket, 1u) == NTOT - 1) ? 1u : 0u;
    __syncthreads();

    if (s_last) {
        __threadfence();            // acquire: all blocks' writes visible
        if (w < BB*KK) {            // warp w reduces channel w's 16 partials
            float A = (lane < NBX) ? g_pA[w][lane] : 0.f;
            float B = (lane < NBX) ? g_pB[w][lane] : 0.f;
            float C = (lane < NBX) ? g_pC[w][lane] : 0.f;
            A = warp_red(A); B = warp_red(B); C = warp_red(C);
            if (lane == 0) jsh[w] = (double)A - (double)B*(double)B/(double)C;
        }
        __syncthreads();
        if (tid == 0) {
            double J1 = 0.0;
            #pragma unroll
            for (int ch = 0; ch < BB*KK; ch++) J1 += jsh[ch];
            double J2 = atomicAdd(&g_J2, 0.0);
            double denom = (double)BB * (double)NN;
            out[0] = (float)((J1 + REG_WT * J2) / denom);
            g_J2 = 0.0;             // self-reset for next launch
            g_ticket = 0u;
        }
    }
}

extern "C" void kernel_launch(void* const* d_in, const int* in_sizes, int n_in,
                              void* d_out, int out_size) {
    const float* yp  = (const float*)d_in[0];   // y_pred [2,4,128,128,128]
    const float* img = (const float*)d_in[1];   // image  [2,1,128,128,128]
    (void)in_sizes; (void)n_in; (void)out_size;

    // Allow 3 blocks/SM worth of shared memory (3 x 41KB = 123KB of 228KB).
    cudaFuncSetAttribute(rfcm_kernel, cudaFuncAttributePreferredSharedMemoryCarveout, 60);
    rfcm_kernel<<<NTOT, dim3(32, TY)>>>(yp, img, (float*)d_out);
}